// round 6
// baseline (speedup 1.0000x reference)
#include <cuda_runtime.h>
#include <cuda_fp16.h>
#include <cstdint>
#include <cstddef>

// ---------------------------------------------------------------- problem shape
#define BATCH 4
#define SEQ   2048
#define NPREV 8
#define DIM   1024
#define HEADS 16
#define HDIM  64
#define TOKENS (BATCH * SEQ)           // 8192
#define KVROWS (TOKENS * NPREV)        // 65536

// ---------------------------------------------------------------- scratch (fp16)
__device__ __half g_cur16 [(size_t)TOKENS * DIM];
__device__ __half g_hist16[(size_t)KVROWS * DIM];
__device__ __half g_wq[(size_t)DIM * DIM];
__device__ __half g_wv[(size_t)DIM * DIM];
__device__ __half g_wo[(size_t)DIM * DIM];
__device__ __half g_wkt[(size_t)HEADS * DIM * HDIM];     // [h][j:1024][d:64] = Wk[h*64+d][j]
__device__ __half g_q16 [(size_t)TOKENS * DIM];
__device__ __half g_qp  [(size_t)HEADS * TOKENS * DIM];  // [h][t][j]  268 MB
__device__ __half g_hmix[(size_t)HEADS * TOKENS * DIM];  // [h][t][j]  268 MB
__device__ __half g_o16 [(size_t)TOKENS * DIM];

// ---------------------------------------------------------------- helpers
__device__ __forceinline__ uint32_t smem_u32(const void* p) {
    uint32_t a;
    asm("{ .reg .u64 t; cvta.to.shared.u64 t, %1; cvt.u32.u64 %0, t; }" : "=r"(a) : "l"(p));
    return a;
}
__device__ __forceinline__ uint32_t swz(uint32_t off) { return off ^ ((off >> 3) & 0x70); }

__device__ __forceinline__ void cpasync16(uint32_t s, const void* g) {
    asm volatile("cp.async.cg.shared.global [%0], [%1], 16;" :: "r"(s), "l"(g));
}
__device__ __forceinline__ void cp_commit() {
    asm volatile("cp.async.commit_group;" ::: "memory");
}
template <int N>
__device__ __forceinline__ void cp_wait() {
    asm volatile("cp.async.wait_group %0;" :: "n"(N) : "memory");
}

__device__ __forceinline__ void ldsm_x4(uint32_t& r0, uint32_t& r1, uint32_t& r2, uint32_t& r3,
                                        uint32_t addr) {
    asm volatile("ldmatrix.sync.aligned.m8n8.x4.shared.b16 {%0,%1,%2,%3}, [%4];"
                 : "=r"(r0), "=r"(r1), "=r"(r2), "=r"(r3) : "r"(addr));
}

__device__ __forceinline__ void mma16816_f16(float* d, const uint32_t* a, const uint32_t* b) {
    asm volatile(
        "mma.sync.aligned.m16n8k16.row.col.f32.f16.f16.f32 "
        "{%0,%1,%2,%3}, {%4,%5,%6,%7}, {%8,%9}, {%0,%1,%2,%3};"
        : "+f"(d[0]), "+f"(d[1]), "+f"(d[2]), "+f"(d[3])
        : "r"(a[0]), "r"(a[1]), "r"(a[2]), "r"(a[3]), "r"(b[0]), "r"(b[1]));
}

// ================================================================ GEMM A: full 1024-K
// C[M,1024] = A*B^T (+addend). 128x128 tile, BK=64, 3-stage, 8 warps (32x64 warp tile).
#define GBM 128
#define GBN 128
#define NCHUNK (DIM / 64)                 // 16
#define MAT_BYTES (128 * 128)
#define STAGE_BYTES (2 * MAT_BYTES)
#define NSTAGE 3
#define SMEM_DYN (NSTAGE * STAGE_BYTES)   // 96 KB

__device__ __forceinline__ void load_stage(
    uint32_t sbase, int tid, const char* A, const char* B,
    long long m0, long long n0, int chunk)
{
    const long long kbyte = (long long)chunk * 128;
#pragma unroll
    for (int i = 0; i < 4; i++) {
        const int u  = tid + i * 256;
        const int r  = u >> 3;
        const int c8 = u & 7;
        const uint32_t so = swz((uint32_t)(r * 128 + c8 * 16));
        cpasync16(sbase + so,             A + (m0 + r) * (DIM * 2) + kbyte + c8 * 16);
        cpasync16(sbase + MAT_BYTES + so, B + (n0 + r) * (DIM * 2) + kbyte + c8 * 16);
    }
}

template <bool F16OUT>
__global__ __launch_bounds__(256, 2) void gemm_f16(
    const __half* __restrict__ A, const __half* __restrict__ B,
    void* __restrict__ Cout, const float* __restrict__ addend)
{
    extern __shared__ char dynsmem[];
    const uint32_t base = smem_u32(dynsmem);

    const int tid = threadIdx.x, lane = tid & 31, wid = tid >> 5;
    const int warp_m = wid & 3, warp_n = wid >> 2;
    const long long m0 = (long long)blockIdx.y * GBM;
    const long long n0 = (long long)blockIdx.x * GBN;
    const char* pA = (const char*)A;
    const char* pB = (const char*)B;

    float acc[2][8][4];
#pragma unroll
    for (int mt = 0; mt < 2; mt++)
#pragma unroll
        for (int nt = 0; nt < 8; nt++)
#pragma unroll
            for (int j = 0; j < 4; j++) acc[mt][nt][j] = 0.f;

    load_stage(base, tid, pA, pB, m0, n0, 0);
    cp_commit();
    load_stage(base + STAGE_BYTES, tid, pA, pB, m0, n0, 1);
    cp_commit();

    const int a_row = warp_m * 32 + (lane & 15);
    const int a_cofs = (lane & 16) ? 16 : 0;
    const int b_row = warp_n * 64 + (lane & 7) + ((lane & 16) ? 8 : 0);
    const int b_cofs = (lane & 8) ? 16 : 0;

    for (int c = 0; c < NCHUNK; ++c) {
        if (c + 2 < NCHUNK) cp_wait<1>(); else cp_wait<0>();
        __syncthreads();
        if (c + 2 < NCHUNK) {
            load_stage(base + ((c + 2) % NSTAGE) * STAGE_BYTES, tid, pA, pB, m0, n0, c + 2);
            cp_commit();
        }
        const uint32_t sA = base + (c % NSTAGE) * STAGE_BYTES;
        const uint32_t sB = sA + MAT_BYTES;
#pragma unroll
        for (int s = 0; s < 4; s++) {
            uint32_t af[2][4], bf[8][2];
#pragma unroll
            for (int mt = 0; mt < 2; mt++) {
                const uint32_t off = swz((uint32_t)((a_row + mt * 16) * 128 + s * 32 + a_cofs));
                ldsm_x4(af[mt][0], af[mt][1], af[mt][2], af[mt][3], sA + off);
            }
#pragma unroll
            for (int np = 0; np < 4; np++) {
                const uint32_t off = swz((uint32_t)((b_row + np * 16) * 128 + s * 32 + b_cofs));
                uint32_t r0, r1, r2, r3;
                ldsm_x4(r0, r1, r2, r3, sB + off);
                bf[np * 2][0] = r0;     bf[np * 2][1] = r1;
                bf[np * 2 + 1][0] = r2; bf[np * 2 + 1][1] = r3;
            }
#pragma unroll
            for (int mt = 0; mt < 2; mt++)
#pragma unroll
                for (int nt = 0; nt < 8; nt++)
                    mma16816_f16(acc[mt][nt], af[mt], bf[nt]);
        }
        __syncthreads();
    }

    const int g = lane >> 2, t = lane & 3;
#pragma unroll
    for (int mt = 0; mt < 2; mt++)
#pragma unroll
        for (int half = 0; half < 2; half++) {
            const long long row = m0 + warp_m * 32 + mt * 16 + g + half * 8;
            const long long colbase = n0 + warp_n * 64;
            if (F16OUT) {
                __half* crow = (__half*)Cout + row * DIM + colbase;
#pragma unroll
                for (int nt = 0; nt < 8; nt++)
                    *reinterpret_cast<__half2*>(crow + nt * 8 + 2 * t) =
                        __floats2half2_rn(acc[mt][nt][half * 2], acc[mt][nt][half * 2 + 1]);
            } else {
                float* crow = (float*)Cout + row * DIM + colbase;
                const float* arow = addend + row * DIM + colbase;
#pragma unroll
                for (int nt = 0; nt < 8; nt++) {
                    float2 v;
                    v.x = acc[mt][nt][half * 2] ;
                    v.y = acc[mt][nt][half * 2 + 1];
                    const float2 a = *reinterpret_cast<const float2*>(arow + nt * 8 + 2 * t);
                    v.x += a.x; v.y += a.y;
                    *reinterpret_cast<float2*>(crow + nt * 8 + 2 * t) = v;
                }
            }
        }
}

// ================================================================ GEMM B: qp (K=64 batched)
// head h: C_h[8192,1024] = q[:, h*64:h*64+64] @ wkt_h[1024,64]^T. Single K-chunk.
__global__ __launch_bounds__(256, 2) void gemm_qp()
{
    __shared__ char sm[2 * 128 * 128];       // A 16KB + B 16KB
    const uint32_t sA = smem_u32(sm);
    const uint32_t sB = sA + 128 * 128;

    const int tid = threadIdx.x, lane = tid & 31, wid = tid >> 5;
    const int warp_m = wid & 3, warp_n = wid >> 2;
    const int h = blockIdx.z;
    const long long m0 = (long long)blockIdx.y * 128;
    const long long n0 = (long long)blockIdx.x * 128;

    const char* A = (const char*)(g_q16 + (size_t)h * HDIM);          // lda = 1024 halfs
    const char* B = (const char*)(g_wkt + (size_t)h * DIM * HDIM);    // 1024 x 64, ldb = 64
    __half* C = g_qp + (size_t)h * TOKENS * DIM;

#pragma unroll
    for (int i = 0; i < 4; i++) {
        const int u  = tid + i * 256;        // 0..1023
        const int r  = u >> 3;
        const int c8 = u & 7;
        const uint32_t so = swz((uint32_t)(r * 128 + c8 * 16));
        cpasync16(sA + so, A + (m0 + r) * (DIM * 2) + c8 * 16);
        cpasync16(sB + so, B + (n0 + r) * (HDIM * 2) + c8 * 16);
    }
    cp_commit();
    cp_wait<0>();
    __syncthreads();

    float acc[2][8][4];
#pragma unroll
    for (int mt = 0; mt < 2; mt++)
#pragma unroll
        for (int nt = 0; nt < 8; nt++)
#pragma unroll
            for (int j = 0; j < 4; j++) acc[mt][nt][j] = 0.f;

    const int a_row = warp_m * 32 + (lane & 15);
    const int a_cofs = (lane & 16) ? 16 : 0;
    const int b_row = warp_n * 64 + (lane & 7) + ((lane & 16) ? 8 : 0);
    const int b_cofs = (lane & 8) ? 16 : 0;

#pragma unroll
    for (int s = 0; s < 4; s++) {
        uint32_t af[2][4], bf[8][2];
#pragma unroll
        for (int mt = 0; mt < 2; mt++) {
            const uint32_t off = swz((uint32_t)((a_row + mt * 16) * 128 + s * 32 + a_cofs));
            ldsm_x4(af[mt][0], af[mt][1], af[mt][2], af[mt][3], sA + off);
        }
#pragma unroll
        for (int np = 0; np < 4; np++) {
            const uint32_t off = swz((uint32_t)((b_row + np * 16) * 128 + s * 32 + b_cofs));
            uint32_t r0, r1, r2, r3;
            ldsm_x4(r0, r1, r2, r3, sB + off);
            bf[np * 2][0] = r0;     bf[np * 2][1] = r1;
            bf[np * 2 + 1][0] = r2; bf[np * 2 + 1][1] = r3;
        }
#pragma unroll
        for (int mt = 0; mt < 2; mt++)
#pragma unroll
            for (int nt = 0; nt < 8; nt++)
                mma16816_f16(acc[mt][nt], af[mt], bf[nt]);
    }

    const int g = lane >> 2, t = lane & 3;
#pragma unroll
    for (int mt = 0; mt < 2; mt++)
#pragma unroll
        for (int half = 0; half < 2; half++) {
            const long long row = m0 + warp_m * 32 + mt * 16 + g + half * 8;
            __half* crow = C + row * DIM + n0 + warp_n * 64;
#pragma unroll
            for (int nt = 0; nt < 8; nt++)
                *reinterpret_cast<__half2*>(crow + nt * 8 + 2 * t) =
                    __floats2half2_rn(acc[mt][nt][half * 2], acc[mt][nt][half * 2 + 1]);
        }
}

// ================================================================ GEMM C: vproj (N=64 batched)
// head h: o[:, h*64:h*64+64] = hmix_h[8192,1024] @ Wv[h*64:h*64+64, :]^T
#define VP_STAGE (128 * 128 + 64 * 128)      // A 16KB + B 8KB = 24KB
#define VP_SMEM (3 * VP_STAGE)               // 72KB

__global__ __launch_bounds__(256, 2) void gemm_vproj()
{
    extern __shared__ char dynsmem[];
    const uint32_t base = smem_u32(dynsmem);

    const int tid = threadIdx.x, lane = tid & 31, wid = tid >> 5;   // warp_m = wid
    const int h = blockIdx.z;
    const long long m0 = (long long)blockIdx.y * 128;

    const char* A = (const char*)(g_hmix + (size_t)h * TOKENS * DIM);
    const char* B = (const char*)(g_wv + (size_t)h * HDIM * DIM);   // 64 x 1024
    __half* C = g_o16 + (size_t)h * HDIM;                            // cols h*64.., ldc 1024

    auto load_vp = [&](int stage, int chunk) {
        const uint32_t sb = base + stage * VP_STAGE;
        const long long kbyte = (long long)chunk * 128;
#pragma unroll
        for (int i = 0; i < 4; i++) {
            const int u = tid + i * 256;
            const int r = u >> 3, c8 = u & 7;
            const uint32_t so = swz((uint32_t)(r * 128 + c8 * 16));
            cpasync16(sb + so, A + (m0 + r) * (DIM * 2) + kbyte + c8 * 16);
        }
#pragma unroll
        for (int i = 0; i < 2; i++) {
            const int u = tid + i * 256;
            const int r = u >> 3, c8 = u & 7;
            const uint32_t so = swz((uint32_t)(r * 128 + c8 * 16));
            cpasync16(sb + 128 * 128 + so, B + r * (DIM * 2) + kbyte + c8 * 16);
        }
    };

    float acc[8][4];
#pragma unroll
    for (int nt = 0; nt < 8; nt++)
#pragma unroll
        for (int j = 0; j < 4; j++) acc[nt][j] = 0.f;

    load_vp(0, 0); cp_commit();
    load_vp(1, 1); cp_commit();

    const int a_row = wid * 16 + (lane & 15);
    const int a_cofs = (lane & 16) ? 16 : 0;
    const int b_row = (lane & 7) + ((lane & 16) ? 8 : 0);
    const int b_cofs = (lane & 8) ? 16 : 0;

    for (int c = 0; c < NCHUNK; ++c) {
        if (c + 2 < NCHUNK) cp_wait<1>(); else cp_wait<0>();
        __syncthreads();
        if (c + 2 < NCHUNK) { load_vp((c + 2) % 3, c + 2); cp_commit(); }

        const uint32_t sA = base + (c % 3) * VP_STAGE;
        const uint32_t sB = sA + 128 * 128;
#pragma unroll
        for (int s = 0; s < 4; s++) {
            uint32_t af[4], bf[8][2];
            {
                const uint32_t off = swz((uint32_t)(a_row * 128 + s * 32 + a_cofs));
                ldsm_x4(af[0], af[1], af[2], af[3], sA + off);
            }
#pragma unroll
            for (int np = 0; np < 4; np++) {
                const uint32_t off = swz((uint32_t)((b_row + np * 16) * 128 + s * 32 + b_cofs));
                uint32_t r0, r1, r2, r3;
                ldsm_x4(r0, r1, r2, r3, sB + off);
                bf[np * 2][0] = r0;     bf[np * 2][1] = r1;
                bf[np * 2 + 1][0] = r2; bf[np * 2 + 1][1] = r3;
            }
#pragma unroll
            for (int nt = 0; nt < 8; nt++)
                mma16816_f16(acc[nt], af, bf[nt]);
        }
        __syncthreads();
    }

    const int g = lane >> 2, t = lane & 3;
#pragma unroll
    for (int half = 0; half < 2; half++) {
        const long long row = m0 + wid * 16 + g + half * 8;
        __half* crow = C + row * DIM;
#pragma unroll
        for (int nt = 0; nt < 8; nt++)
            *reinterpret_cast<__half2*>(crow + nt * 8 + 2 * t) =
                __floats2half2_rn(acc[nt][half * 2], acc[nt][half * 2 + 1]);
    }
}

// ================================================================ converts
__global__ __launch_bounds__(256) void tohalf_kernel(
    const float4* __restrict__ x, __half2* __restrict__ y, int n4)
{
    const int i = blockIdx.x * blockDim.x + threadIdx.x;
    if (i >= n4) return;
    const float4 v = x[i];
    y[i * 2 + 0] = __floats2half2_rn(v.x, v.y);
    y[i * 2 + 1] = __floats2half2_rn(v.z, v.w);
}

// wkt[h][j][d] = Wk[h*64+d][j]
__global__ __launch_bounds__(256) void wkt_kernel(const float* __restrict__ Wk)
{
    const int idx = blockIdx.x * blockDim.x + threadIdx.x;   // 1M
    const int h = idx >> 16;
    const int j = (idx >> 6) & 1023;
    const int d = idx & 63;
    g_wkt[idx] = __float2half(Wk[(h * HDIM + d) * DIM + j]);
}

// ================================================================ fused attention
// One CTA per token. logits (vs raw history) -> softmax -> hmix, all in one pass.
__global__ __launch_bounds__(256) void attn_fused()
{
    __shared__ __half2 hist2[NPREV * 512];      // 8 x 1024 halfs = 16KB

    const int t = blockIdx.x;
    const int tid = threadIdx.x;
    const int lane = tid & 31;
    const int wid = tid >> 5;

    // load history for this token
    {
        const uint4* src = reinterpret_cast<const uint4*>(g_hist16 + (size_t)t * NPREV * DIM);
        uint4* dst = reinterpret_cast<uint4*>(hist2);
#pragma unroll
        for (int i = 0; i < 4; i++) dst[tid + i * 256] = src[tid + i * 256];
    }
    __syncthreads();

#pragma unroll
    for (int hh = 0; hh < 2; hh++) {
        const int h = wid + hh * 8;
        const __half2* qp2 = reinterpret_cast<const __half2*>(
            g_qp + ((size_t)h * TOKENS + t) * DIM);

        __half2 q2[16];
#pragma unroll
        for (int i = 0; i < 16; i++) q2[i] = qp2[lane + 32 * i];

        float logits[NPREV];
#pragma unroll
        for (int n = 0; n < NPREV; n++) {
            float p = 0.f;
#pragma unroll
            for (int i = 0; i < 16; i++) {
                const float2 a = __half22float2(q2[i]);
                const float2 b = __half22float2(hist2[n * 512 + lane + 32 * i]);
                p += a.x * b.x + a.y * b.y;
            }
#pragma unroll
            for (int off = 16; off > 0; off >>= 1)
                p += __shfl_xor_sync(0xFFFFFFFFu, p, off);
            logits[n] = p * 0.125f;
        }

        float mx = logits[0];
#pragma unroll
        for (int n = 1; n < NPREV; n++) mx = fmaxf(mx, logits[n]);
        float w[NPREV], den = 0.f;
#pragma unroll
        for (int n = 0; n < NPREV; n++) { w[n] = __expf(logits[n] - mx); den += w[n]; }
        const float inv = 1.f / den;
#pragma unroll
        for (int n = 0; n < NPREV; n++) w[n] *= inv;

        __half2* out2 = reinterpret_cast<__half2*>(
            g_hmix + ((size_t)h * TOKENS + t) * DIM);
#pragma unroll
        for (int i = 0; i < 16; i++) {
            float sx = 0.f, sy = 0.f;
#pragma unroll
            for (int n = 0; n < NPREV; n++) {
                const float2 b = __half22float2(hist2[n * 512 + lane + 32 * i]);
                sx += w[n] * b.x;
                sy += w[n] * b.y;
            }
            out2[lane + 32 * i] = __floats2half2_rn(sx, sy);
        }
    }
}

// ================================================================ launch
extern "C" void kernel_launch(void* const* d_in, const int* in_sizes, int n_in,
                              void* d_out, int out_size)
{
    const float* current = (const float*)d_in[0];
    const float* history = (const float*)d_in[1];
    const float* Wq      = (const float*)d_in[2];
    const float* Wk      = (const float*)d_in[3];
    const float* Wv      = (const float*)d_in[4];
    const float* Wo      = (const float*)d_in[5];
    float*       out     = (float*)d_out;

    __half *cur16, *hist16, *wq, *wv, *wo, *q16, *o16;
    cudaGetSymbolAddress((void**)&cur16,  g_cur16);
    cudaGetSymbolAddress((void**)&hist16, g_hist16);
    cudaGetSymbolAddress((void**)&wq,     g_wq);
    cudaGetSymbolAddress((void**)&wv,     g_wv);
    cudaGetSymbolAddress((void**)&wo,     g_wo);
    cudaGetSymbolAddress((void**)&q16,    g_q16);
    cudaGetSymbolAddress((void**)&o16,    g_o16);

    cudaFuncSetAttribute(gemm_f16<true>,  cudaFuncAttributeMaxDynamicSharedMemorySize, SMEM_DYN);
    cudaFuncSetAttribute(gemm_f16<false>, cudaFuncAttributeMaxDynamicSharedMemorySize, SMEM_DYN);
    cudaFuncSetAttribute(gemm_vproj,      cudaFuncAttributeMaxDynamicSharedMemorySize, VP_SMEM);

    const size_t WN = (size_t)DIM * DIM;

    // converts
    tohalf_kernel<<<TOKENS * DIM / 4 / 256, 256>>>((const float4*)current, (__half2*)cur16,
                                                   TOKENS * DIM / 4);
    tohalf_kernel<<<(int)((size_t)KVROWS * DIM / 4 / 256), 256>>>(
        (const float4*)history, (__half2*)hist16, (int)((size_t)KVROWS * DIM / 4));
    tohalf_kernel<<<(int)(WN / 4 / 256), 256>>>((const float4*)Wq, (__half2*)wq, (int)(WN / 4));
    tohalf_kernel<<<(int)(WN / 4 / 256), 256>>>((const float4*)Wv, (__half2*)wv, (int)(WN / 4));
    tohalf_kernel<<<(int)(WN / 4 / 256), 256>>>((const float4*)Wo, (__half2*)wo, (int)(WN / 4));
    wkt_kernel<<<(int)(WN / 256), 256>>>(Wk);

    // q = current @ Wq^T
    gemm_f16<true><<<dim3(DIM / GBN, TOKENS / GBM), 256, SMEM_DYN>>>(cur16, wq, q16, nullptr);

    // q' per head
    gemm_qp<<<dim3(DIM / 128, TOKENS / 128, HEADS), 256>>>();

    // fused logits + softmax + hmix
    attn_fused<<<TOKENS, 256>>>();

    // per-head V projection
    gemm_vproj<<<dim3(1, TOKENS / 128, HEADS), 256, VP_SMEM>>>();

    // out = current + o @ Wo^T
    gemm_f16<false><<<dim3(DIM / GBN, TOKENS / GBM), 256, SMEM_DYN>>>(o16, wo, out, current);
}